// round 15
// baseline (speedup 1.0000x reference)
#include <cuda_runtime.h>
#include <cuda_bf16.h>
#include <cuda_fp16.h>
#include <cuda_fp8.h>
#include <cstdint>

#define N_NODES 20000
#define M_EDGES 5000
#define D_IN    256
#define D_OUT   512
#define NNZ_CAP 5400000
#define N_PAD   20096            // 157 * 128

// ===================== fp8 helpers =========================================
__device__ __forceinline__ float2 f8x2_to_f2(unsigned short v) {
    __half2_raw hr = __nv_cvt_fp8x2_to_halfraw2((__nv_fp8x2_storage_t)v, __NV_E4M3);
    __half2 h = *reinterpret_cast<__half2*>(&hr);
    return __half22float2(h);
}
__device__ __forceinline__ unsigned short f2_to_f8x2(float2 f) {
    return (unsigned short)__nv_cvt_float2_to_fp8x2(f, __NV_SATFINITE, __NV_E4M3);
}

// ===================== scratch (static device globals) =====================
// NOTE: counters rely on CUDA zero-initialization of __device__ globals for
// the FIRST kernel_launch call; every call re-zeroes them in k_ln's tail, so
// each graph replay starts from a clean state (deterministic per call).
__device__ int g_cnt_e[M_EDGES];
__device__ int g_cnt_v[N_NODES];
__device__ int g_eoff[M_EDGES + 1];
__device__ int g_voff[N_NODES + 1];
__device__ int g_ecur[M_EDGES];
__device__ int g_vcur[N_NODES];
__device__ int g_npairs;
__device__ unsigned int g_pairs[NNZ_CAP];      // (n << 13) | m
__device__ int g_edge_nodes[NNZ_CAP];
__device__ int g_node_edges[NNZ_CAP];
__device__ unsigned short g_xf8[N_NODES * 128];   // x in fp8x2 (5 MB, L2-resident)
__device__ unsigned short g_Af8[M_EDGES * 128];   // edge feats fp8x2 (1.25 MB)
__device__ float g_B[N_NODES * D_IN];
__device__ float g_h[N_NODES * D_OUT];
__device__ __nv_bfloat16 g_Acat[(size_t)N_PAD * 1024];   // [Bbf | x_hi | x_hi | x_lo]
__device__ __nv_bfloat16 g_Wt[512 * 1024];               // transposed stacked weights

// ---------------- 1: single H pass: counts + packed pairs + x->fp8 ---------
__global__ void k_count_pairs(const float4* __restrict__ H4,
                              const float2* __restrict__ x2) {
    int i = blockIdx.x * blockDim.x + threadIdx.x;
    // fused x -> fp8 cast (first 2.56M threads, one element each)
    if (i < N_NODES * 128) g_xf8[i] = f2_to_f8x2(x2[i]);

    const int total = N_NODES * (M_EDGES / 4);
    float4 v = make_float4(0.f, 0.f, 0.f, 0.f);
    if (i < total) v = H4[i];
    int base = i * 4;
    int n = base / M_EDGES;
    int m = base - n * M_EDGES;
    int ms[4]; int vc = 0;
    if (v.x != 0.f) { atomicAdd(&g_cnt_e[m + 0], 1); ms[vc++] = m + 0; }
    if (v.y != 0.f) { atomicAdd(&g_cnt_e[m + 1], 1); ms[vc++] = m + 1; }
    if (v.z != 0.f) { atomicAdd(&g_cnt_e[m + 2], 1); ms[vc++] = m + 2; }
    if (v.w != 0.f) { atomicAdd(&g_cnt_e[m + 3], 1); ms[vc++] = m + 3; }
    const unsigned full = 0xffffffffu;
    int lane = threadIdx.x & 31;
    // node-degree: one atomic per warp when the warp is row-uniform (~97%)
    int n0 = __shfl_sync(full, n, 0);
    bool uni = __all_sync(full, n == n0);
    if (uni) {
        int vsum = vc;
        #pragma unroll
        for (int o = 16; o > 0; o >>= 1) vsum += __shfl_xor_sync(full, vsum, o);
        if (lane == 0 && vsum) atomicAdd(&g_cnt_v[n0], vsum);
    } else if (vc) {
        atomicAdd(&g_cnt_v[n], vc);
    }
    // warp-aggregated pair append
    int incl = vc;
    #pragma unroll
    for (int o = 1; o < 32; o <<= 1) {
        int t = __shfl_up_sync(full, incl, o);
        if (lane >= o) incl += t;
    }
    int tot = __shfl_sync(full, incl, 31);
    int wbase = 0;
    if (lane == 31 && tot) wbase = atomicAdd(&g_npairs, tot);
    wbase = __shfl_sync(full, wbase, 31);
    int off = wbase + incl - vc;
    for (int j = 0; j < vc; ++j)
        if (off + j < NNZ_CAP) g_pairs[off + j] = ((unsigned)n << 13) | (unsigned)ms[j];
}

// ---------------- 2: both exclusive scans, O(n), 2 parallel blocks ---------
__device__ __forceinline__ void scan_phase(const int* cnt, int* off, int len,
                                           int* part) {
    int t = threadIdx.x;
    int chunk = (len + 1023) / 1024;
    int beg = t * chunk;
    int end = beg + chunk; if (end > len) end = len;
    if (beg > len) beg = len;
    int s = 0;
    for (int i = beg; i < end; ++i) s += cnt[i];
    part[t] = s;
    __syncthreads();
    #pragma unroll
    for (int o = 1; o < 1024; o <<= 1) {
        int v = (t >= o) ? part[t - o] : 0;
        __syncthreads();
        part[t] += v;
        __syncthreads();
    }
    int run = part[t] - s;   // exclusive prefix of this chunk
    for (int i = beg; i < end; ++i) { off[i] = run; run += cnt[i]; }
    if (t == 1023) off[len] = part[1023];
}
__global__ void k_scan2() {
    __shared__ int part[1024];
    if (blockIdx.x == 0) scan_phase(g_cnt_e, g_eoff, M_EDGES, part);
    else                 scan_phase(g_cnt_v, g_voff, N_NODES, part);
}

// ---------------- 3: scatter pairs into CSC + CSR, ILP x4 ------------------
__global__ void k_scatter() {
    int np = g_npairs; if (np > NNZ_CAP) np = NNZ_CAP;
    int nq = np >> 2;                       // full groups of 4
    int stride = gridDim.x * blockDim.x;
    const uint4* pairs4 = reinterpret_cast<const uint4*>(g_pairs);
    for (int q = blockIdx.x * blockDim.x + threadIdx.x; q < nq; q += stride) {
        uint4 pv = pairs4[q];
        unsigned p[4] = {pv.x, pv.y, pv.z, pv.w};
        int nn[4], mm[4], ia[4], ib[4];
        #pragma unroll
        for (int j = 0; j < 4; ++j) { nn[j] = (int)(p[j] >> 13); mm[j] = (int)(p[j] & 0x1FFFu); }
        // edge side: issue all 4 atomics back-to-back (independent addrs)
        #pragma unroll
        for (int j = 0; j < 4; ++j) ia[j] = g_eoff[mm[j]] + atomicAdd(&g_ecur[mm[j]], 1);
        // node side: consecutive pairs usually share n -> single aggregated atomic
        if (nn[0] == nn[3] && nn[0] == nn[1] && nn[0] == nn[2]) {
            int b0 = atomicAdd(&g_vcur[nn[0]], 4);
            int vb = g_voff[nn[0]];
            #pragma unroll
            for (int j = 0; j < 4; ++j) ib[j] = vb + b0 + j;
        } else {
            #pragma unroll
            for (int j = 0; j < 4; ++j) ib[j] = g_voff[nn[j]] + atomicAdd(&g_vcur[nn[j]], 1);
        }
        #pragma unroll
        for (int j = 0; j < 4; ++j) {
            if (ia[j] < NNZ_CAP) g_edge_nodes[ia[j]] = nn[j];
            if (ib[j] < NNZ_CAP) g_node_edges[ib[j]] = mm[j];
        }
    }
    // tail (< 4 pairs)
    int t0 = nq << 2;
    int gid = blockIdx.x * blockDim.x + threadIdx.x;
    if (gid < np - t0) {
        unsigned p = g_pairs[t0 + gid];
        int n = (int)(p >> 13), m = (int)(p & 0x1FFFu);
        int a = g_eoff[m] + atomicAdd(&g_ecur[m], 1);
        int b = g_voff[n] + atomicAdd(&g_vcur[n], 1);
        if (a < NNZ_CAP) g_edge_nodes[a] = n;
        if (b < NNZ_CAP) g_node_edges[b] = m;
    }
}

// ---------------- 4: edge aggregation (fp8 gathers, unroll 8) --------------
__global__ void __launch_bounds__(128) k_edge_agg() {
    int m = blockIdx.x;
    int beg = g_eoff[m]; int end = g_eoff[m + 1];
    if (end > NNZ_CAP) end = NNZ_CAP;
    if (beg > NNZ_CAP) beg = NNZ_CAP;
    int k = threadIdx.x;
    float sx = 0.f, sy = 0.f;
    int i = beg;
    for (; i + 8 <= end; i += 8) {
        int idx[8];
        #pragma unroll
        for (int j = 0; j < 8; ++j) idx[j] = g_edge_nodes[i + j];
        unsigned short raw[8];
        #pragma unroll
        for (int j = 0; j < 8; ++j) raw[j] = g_xf8[idx[j] * 128 + k];
        #pragma unroll
        for (int j = 0; j < 8; ++j) {
            float2 f = f8x2_to_f2(raw[j]);
            sx += f.x; sy += f.y;
        }
    }
    for (; i < end; ++i) {
        float2 f0 = f8x2_to_f2(g_xf8[g_edge_nodes[i] * 128 + k]);
        sx += f0.x; sy += f0.y;
    }
    float inv = 1.f / fmaxf((float)g_cnt_e[m], 1.f);
    g_Af8[m * 128 + k] = f2_to_f8x2(make_float2(sx * inv, sy * inv));
}

// ---------------- 5: node aggregation (fp8 gathers, unroll 8) --------------
__global__ void __launch_bounds__(128) k_node_agg() {
    int n = blockIdx.x;
    int beg = g_voff[n]; int end = g_voff[n + 1];
    if (end > NNZ_CAP) end = NNZ_CAP;
    if (beg > NNZ_CAP) beg = NNZ_CAP;
    int k = threadIdx.x;
    float sx = 0.f, sy = 0.f;
    int i = beg;
    for (; i + 8 <= end; i += 8) {
        int idx[8];
        #pragma unroll
        for (int j = 0; j < 8; ++j) idx[j] = g_node_edges[i + j];
        unsigned short raw[8];
        #pragma unroll
        for (int j = 0; j < 8; ++j) raw[j] = g_Af8[idx[j] * 128 + k];
        #pragma unroll
        for (int j = 0; j < 8; ++j) {
            float2 f = f8x2_to_f2(raw[j]);
            sx += f.x; sy += f.y;
        }
    }
    for (; i < end; ++i) {
        float2 f0 = f8x2_to_f2(g_Af8[g_node_edges[i] * 128 + k]);
        sx += f0.x; sy += f0.y;
    }
    float inv = 1.f / fmaxf((float)g_cnt_v[n], 1.f);
    reinterpret_cast<float2*>(g_B)[n * 128 + k] = make_float2(sx * inv, sy * inv);
}

// ---------------- 6a: build A_cat = [bf16(B) | x_hi | x_hi | x_lo] ---------
__global__ void __launch_bounds__(512) k_prep_A(const float2* __restrict__ x2) {
    int row = blockIdx.x;
    int p = threadIdx.x;                 // bf162-pair index 0..511
    __nv_bfloat162* dst = reinterpret_cast<__nv_bfloat162*>(g_Acat) + (size_t)row * 512 + p;
    if (p < 128) {
        float2 f = reinterpret_cast<const float2*>(g_B)[row * 128 + p];
        *dst = __floats2bfloat162_rn(f.x, f.y);
    } else if (p < 384) {
        int q = (p < 256) ? (p - 128) : (p - 256);
        float2 f = x2[row * 128 + q];
        *dst = __floats2bfloat162_rn(f.x, f.y);      // x_hi
    } else {
        int q = p - 384;
        float2 f = x2[row * 128 + q];
        __nv_bfloat16 hx = __float2bfloat16_rn(f.x);
        __nv_bfloat16 hy = __float2bfloat16_rn(f.y);
        __nv_bfloat16 lx = __float2bfloat16_rn(f.x - __bfloat162float(hx));
        __nv_bfloat16 ly = __float2bfloat16_rn(f.y - __bfloat162float(hy));
        *dst = __halves2bfloat162(lx, ly);           // x_lo
    }
}

// ---------------- 6b: build W_t[n, k] = stackedW[k, n] ---------------------
__global__ void __launch_bounds__(256) k_prep_W(const float* __restrict__ Wn,
                                               const float* __restrict__ Wr) {
    int i = blockIdx.x * blockDim.x + threadIdx.x;   // i = n*1024 + k
    if (i >= 512 * 1024) return;
    int n = i >> 10;
    int k = i & 1023;
    __nv_bfloat16 v;
    if (k < 256) {
        v = __float2bfloat16_rn(Wn[k * 512 + n]);
    } else if (k < 512) {
        v = __float2bfloat16_rn(Wr[(k - 256) * 512 + n]);                 // hi
    } else if (k < 768) {
        float f = Wr[(k - 512) * 512 + n];
        __nv_bfloat16 h = __float2bfloat16_rn(f);
        v = __float2bfloat16_rn(f - __bfloat162float(h));                 // lo
    } else {
        v = __float2bfloat16_rn(Wr[(k - 768) * 512 + n]);                 // hi
    }
    g_Wt[(size_t)n * 1024 + k] = v;
}

// ---------------- 7: HMMA bf16 GEMM  h = A_cat @ W_t^T ---------------------
__device__ __forceinline__ void mma16816(float* c, const uint32_t* a, const uint32_t* b) {
    asm volatile(
        "mma.sync.aligned.m16n8k16.row.col.f32.bf16.bf16.f32 "
        "{%0,%1,%2,%3}, {%4,%5,%6,%7}, {%8,%9}, {%0,%1,%2,%3};\n"
        : "+f"(c[0]), "+f"(c[1]), "+f"(c[2]), "+f"(c[3])
        : "r"(a[0]), "r"(a[1]), "r"(a[2]), "r"(a[3]), "r"(b[0]), "r"(b[1]));
}

#define ASTRIDE 72   // 64 + 8 bf16 pad: fragment LDS banks conflict-free

__global__ void __launch_bounds__(256) k_gemm() {
    __shared__ __nv_bfloat16 As[128][ASTRIDE];
    __shared__ __nv_bfloat16 Bs[64][ASTRIDE];
    int tid = threadIdx.x;
    int lane = tid & 31;
    int warp = tid >> 5;
    int warp_m = warp & 3;
    int warp_n = warp >> 2;
    int rowBase = blockIdx.y * 128;
    int colBase = blockIdx.x * 64;

    int srow = tid >> 3;
    int scol = tid & 7;

    float acc[2][4][4];
    #pragma unroll
    for (int i = 0; i < 2; ++i)
        #pragma unroll
        for (int j = 0; j < 4; ++j)
            #pragma unroll
            for (int q = 0; q < 4; ++q) acc[i][j][q] = 0.f;

    const uint4* gA = reinterpret_cast<const uint4*>(g_Acat);
    const uint4* gB = reinterpret_cast<const uint4*>(g_Wt);

    for (int kc = 0; kc < 16; ++kc) {
        int kq = kc * 8 + scol;
        uint4 sa[4], sb[2];
        #pragma unroll
        for (int p = 0; p < 4; ++p)
            sa[p] = gA[(size_t)(rowBase + p * 32 + srow) * 128 + kq];
        #pragma unroll
        for (int p = 0; p < 2; ++p)
            sb[p] = gB[(size_t)(colBase + p * 32 + srow) * 128 + kq];

        __syncthreads();
        #pragma unroll
        for (int p = 0; p < 4; ++p)
            *reinterpret_cast<uint4*>(&As[p * 32 + srow][scol * 8]) = sa[p];
        #pragma unroll
        for (int p = 0; p < 2; ++p)
            *reinterpret_cast<uint4*>(&Bs[p * 32 + srow][scol * 8]) = sb[p];
        __syncthreads();

        #pragma unroll
        for (int k0 = 0; k0 < 64; k0 += 16) {
            uint32_t af[2][4], bf[4][2];
            int c = k0 + (lane & 3) * 2;
            #pragma unroll
            for (int tm = 0; tm < 2; ++tm) {
                int r = warp_m * 32 + tm * 16 + (lane >> 2);
                af[tm][0] = *reinterpret_cast<const uint32_t*>(&As[r][c]);
                af[tm][1] = *reinterpret_cast<const uint32_t*>(&As[r + 8][c]);
                af[tm][2] = *reinterpret_cast<const uint32_t*>(&As[r][c + 8]);
                af[tm][3] = *reinterpret_cast<const uint32_t*>(&As[r + 8][c + 8]);
            }
            #pragma unroll
            for (int tn = 0; tn < 4; ++tn) {
                int nr = warp_n * 32 + tn * 8 + (lane >> 2);
                bf[tn][0] = *reinterpret_cast<const uint32_t*>(&Bs[nr][c]);
                bf[tn][1] = *reinterpret_cast<const uint32_t*>(&Bs[nr][c + 8]);
            }
            #pragma unroll
            for (int tm = 0; tm < 2; ++tm)
                #pragma unroll
                for (int tn = 0; tn < 4; ++tn)
                    mma16816(acc[tm][tn], af[tm], bf[tn]);
        }
    }

    #pragma unroll
    for (int tm = 0; tm < 2; ++tm) {
        int r0 = rowBase + warp_m * 32 + tm * 16 + (lane >> 2);
        #pragma unroll
        for (int tn = 0; tn < 4; ++tn) {
            int c = colBase + warp_n * 32 + tn * 8 + (lane & 3) * 2;
            if (r0 < N_NODES)
                *reinterpret_cast<float2*>(&g_h[(size_t)r0 * D_OUT + c]) =
                    make_float2(acc[tm][tn][0], acc[tm][tn][1]);
            if (r0 + 8 < N_NODES)
                *reinterpret_cast<float2*>(&g_h[(size_t)(r0 + 8) * D_OUT + c]) =
                    make_float2(acc[tm][tn][2], acc[tm][tn][3]);
        }
    }
}

// ---------------- 8: LayerNorm + counter re-zero for next replay -----------
__global__ void __launch_bounds__(256) k_ln(const float* __restrict__ gamma,
                                            const float* __restrict__ beta,
                                            float* __restrict__ out) {
    int row = blockIdx.x;
    int t = threadIdx.x;
    // tail zeroing: resets counters so the next kernel_launch starts clean
    int gid = row * 256 + t;
    if (gid < M_EDGES) { g_cnt_e[gid] = 0; g_ecur[gid] = 0; }
    if (gid < N_NODES) { g_cnt_v[gid] = 0; g_vcur[gid] = 0; }
    if (gid == 0) g_npairs = 0;

    const float* h = g_h + (size_t)row * D_OUT;
    float v0 = h[t], v1 = h[t + 256];
    float s = v0 + v1;
    float sq = v0 * v0 + v1 * v1;
    #pragma unroll
    for (int o = 16; o > 0; o >>= 1) {
        s  += __shfl_xor_sync(0xffffffffu, s,  o);
        sq += __shfl_xor_sync(0xffffffffu, sq, o);
    }
    __shared__ float ssum[8], ssq[8];
    __shared__ float s_mu, s_inv;
    int w = t >> 5, l = t & 31;
    if (l == 0) { ssum[w] = s; ssq[w] = sq; }
    __syncthreads();
    if (t == 0) {
        float ts = 0.f, tq = 0.f;
        #pragma unroll
        for (int i = 0; i < 8; ++i) { ts += ssum[i]; tq += ssq[i]; }
        float mu = ts * (1.f / (float)D_OUT);
        float var = tq * (1.f / (float)D_OUT) - mu * mu;
        s_mu = mu;
        s_inv = rsqrtf(var + 1e-5f);
    }
    __syncthreads();
    float mu = s_mu, inv = s_inv;
    out[(size_t)row * D_OUT + t]       = (v0 - mu) * inv * gamma[t]       + beta[t];
    out[(size_t)row * D_OUT + t + 256] = (v1 - mu) * inv * gamma[t + 256] + beta[t + 256];
}

// ---------------- launch ----------------------------------------------------
extern "C" void kernel_launch(void* const* d_in, const int* in_sizes, int n_in,
                              void* d_out, int out_size) {
    const float* x     = (const float*)d_in[0];
    const float* H     = (const float*)d_in[1];
    const float* Wn    = (const float*)d_in[2];
    const float* Wr    = (const float*)d_in[3];
    const float* gamma = (const float*)d_in[4];
    const float* beta  = (const float*)d_in[5];
    float* out = (float*)d_out;

    const int total4 = N_NODES * (M_EDGES / 4);
    k_count_pairs<<<(total4 + 255) / 256, 256>>>((const float4*)H, (const float2*)x);
    k_scan2<<<2, 1024>>>();
    k_scatter<<<2048, 256>>>();

    k_edge_agg<<<M_EDGES, 128>>>();     // 4th launch -> ncu capture slot
    k_node_agg<<<N_NODES, 128>>>();

    k_prep_W<<<(512 * 1024 + 255) / 256, 256>>>(Wn, Wr);
    k_prep_A<<<N_NODES, 512>>>((const float2*)x);

    dim3 ggrid(D_OUT / 64, N_PAD / 128);   // (8, 157)
    k_gemm<<<ggrid, 256>>>();

    k_ln<<<N_NODES, 256>>>(gamma, beta, out);
}

// round 17
// speedup vs baseline: 1.6307x; 1.6307x over previous
#include <cuda_runtime.h>
#include <cuda_bf16.h>
#include <cstdint>

#define N_NODES 20000
#define M_EDGES 5000
#define D_IN    256
#define D_OUT   512
#define N_PAD   20096            // 157 * 128 (rows for gemm2/F)
#define HM_PAD  5120             // edge dim padded (80 * 64)
#define HN_PAD  20032            // node dim padded (313 * 64)

// ===================== scratch (static device globals) =====================
// Pad regions of g_Hbf / g_HbfT / g_xbfT are NEVER written by any kernel:
// they stay at CUDA's zero-initialization forever -> zero contributions.
// g_de / g_dv are atomically accumulated each call and re-zeroed in k_ln's
// tail, so every graph replay starts clean (deterministic per call).
__device__ __nv_bfloat16 g_Hbf[(size_t)N_PAD * HM_PAD];    // H  [n, m] 205.8 MB
__device__ __nv_bfloat16 g_HbfT[(size_t)HM_PAD * HN_PAD];  // H^T[m, n] 205.1 MB
__device__ __nv_bfloat16 g_xbfT[(size_t)D_IN * HN_PAD];    // x^T[d, n] 10.3 MB
__device__ float g_C1[(size_t)HM_PAD * D_IN];              // H^T@x raw   5.2 MB
__device__ __nv_bfloat16 g_A1T[(size_t)D_IN * HM_PAD];     // (edge feat)^T 2.6 MB
__device__ float g_de[HM_PAD];
__device__ float g_dv[N_NODES];
__device__ float g_h[(size_t)N_NODES * D_OUT];
__device__ __nv_bfloat16 g_Acat[(size_t)N_PAD * 1024];     // [Bbf | x_hi | x_hi | x_lo]
__device__ __nv_bfloat16 g_Wt[512 * 1024];

// ---------------- 1: x -> x^T bf16 (tiled transpose) -----------------------
__global__ void __launch_bounds__(256) k_xt(const float* __restrict__ x) {
    __shared__ __nv_bfloat16 sb[64][65];
    int n0 = blockIdx.x * 64;          // 313 tiles
    int d0 = blockIdx.y * 64;          // 4 tiles
    int t = threadIdx.x;
    #pragma unroll
    for (int p = 0; p < 4; ++p) {
        int n_l = p * 16 + (t >> 4);
        int d_l = (t & 15) * 4;
        int n = n0 + n_l;
        float4 v = make_float4(0.f, 0.f, 0.f, 0.f);
        if (n < N_NODES) v = *reinterpret_cast<const float4*>(x + (size_t)n * D_IN + d0 + d_l);
        sb[n_l][d_l + 0] = __float2bfloat16_rn(v.x);
        sb[n_l][d_l + 1] = __float2bfloat16_rn(v.y);
        sb[n_l][d_l + 2] = __float2bfloat16_rn(v.z);
        sb[n_l][d_l + 3] = __float2bfloat16_rn(v.w);
    }
    __syncthreads();
    #pragma unroll
    for (int q = 0; q < 4; ++q) {
        int d_l = q * 16 + (t >> 4);
        int n_l = (t & 15) * 4;
        if (n0 + n_l < N_NODES) {
            __nv_bfloat16 o[4];
            #pragma unroll
            for (int j = 0; j < 4; ++j) o[j] = sb[n_l + j][d_l];
            *reinterpret_cast<uint2*>(g_xbfT + (size_t)(d0 + d_l) * HN_PAD + n0 + n_l) =
                *reinterpret_cast<uint2*>(o);
        }
    }
}

// ---------------- 2: H -> Hbf + HbfT + degree sums --------------------------
__global__ void __launch_bounds__(256) k_prep(const float* __restrict__ H) {
    __shared__ __nv_bfloat16 sb[64][65];
    int m0 = blockIdx.x * 64;          // 79 tiles (last partial)
    int n0 = blockIdx.y * 64;          // 313 tiles (last partial)
    int t = threadIdx.x;
    const unsigned full = 0xffffffffu;
    #pragma unroll
    for (int p = 0; p < 4; ++p) {
        int n_l = p * 16 + (t >> 4);
        int m_l = (t & 15) * 4;
        int n = n0 + n_l;
        int mg = m0 + m_l;
        float4 v = make_float4(0.f, 0.f, 0.f, 0.f);
        if (n < N_NODES && mg < M_EDGES)   // M_EDGES % 4 == 0 -> full vec or nothing
            v = *reinterpret_cast<const float4*>(H + (size_t)n * M_EDGES + mg);
        __nv_bfloat16 b[4] = {__float2bfloat16_rn(v.x), __float2bfloat16_rn(v.y),
                              __float2bfloat16_rn(v.z), __float2bfloat16_rn(v.w)};
        if (n < N_NODES && mg < M_EDGES)
            *reinterpret_cast<uint2*>(g_Hbf + (size_t)n * HM_PAD + mg) =
                *reinterpret_cast<uint2*>(b);
        sb[n_l][m_l + 0] = b[0]; sb[n_l][m_l + 1] = b[1];
        sb[n_l][m_l + 2] = b[2]; sb[n_l][m_l + 3] = b[3];
        // row (node) degree partial: reduce 16 lanes
        float s = v.x + v.y + v.z + v.w;
        #pragma unroll
        for (int o = 8; o > 0; o >>= 1) s += __shfl_down_sync(full, s, o, 16);
        if ((t & 15) == 0 && n < N_NODES && s != 0.f) atomicAdd(&g_dv[n], s);
    }
    __syncthreads();
    #pragma unroll
    for (int q = 0; q < 4; ++q) {
        int m_l = q * 16 + (t >> 4);
        int n_l = (t & 15) * 4;
        int mg = m0 + m_l;
        __nv_bfloat16 o[4];
        #pragma unroll
        for (int j = 0; j < 4; ++j) o[j] = sb[n_l + j][m_l];
        if (mg < M_EDGES)
            *reinterpret_cast<uint2*>(g_HbfT + (size_t)mg * HN_PAD + n0 + n_l) =
                *reinterpret_cast<uint2*>(o);
        float cs = __bfloat162float(o[0]) + __bfloat162float(o[1]) +
                   __bfloat162float(o[2]) + __bfloat162float(o[3]);
        #pragma unroll
        for (int oo = 8; oo > 0; oo >>= 1) cs += __shfl_down_sync(full, cs, oo, 16);
        if ((t & 15) == 0 && mg < M_EDGES && cs != 0.f) atomicAdd(&g_de[mg], cs);
    }
}

// ---------------- 3: W_t builder (unchanged) --------------------------------
__global__ void __launch_bounds__(256) k_prep_W(const float* __restrict__ Wn,
                                               const float* __restrict__ Wr) {
    int i = blockIdx.x * blockDim.x + threadIdx.x;
    if (i >= 512 * 1024) return;
    int n = i >> 10;
    int k = i & 1023;
    __nv_bfloat16 v;
    if (k < 256) {
        v = __float2bfloat16_rn(Wn[k * 512 + n]);
    } else if (k < 512) {
        v = __float2bfloat16_rn(Wr[(k - 256) * 512 + n]);
    } else if (k < 768) {
        float f = Wr[(k - 512) * 512 + n];
        __nv_bfloat16 h = __float2bfloat16_rn(f);
        v = __float2bfloat16_rn(f - __bfloat162float(h));
    } else {
        v = __float2bfloat16_rn(Wr[(k - 768) * 512 + n]);
    }
    g_Wt[(size_t)n * 1024 + k] = v;
}

// ---------------- generic HMMA GEMM (templated), reg-prefetch ---------------
__device__ __forceinline__ void mma16816(float* c, const uint32_t* a, const uint32_t* b) {
    asm volatile(
        "mma.sync.aligned.m16n8k16.row.col.f32.bf16.bf16.f32 "
        "{%0,%1,%2,%3}, {%4,%5,%6,%7}, {%8,%9}, {%0,%1,%2,%3};\n"
        : "+f"(c[0]), "+f"(c[1]), "+f"(c[2]), "+f"(c[3])
        : "r"(a[0]), "r"(a[1]), "r"(a[2]), "r"(a[3]), "r"(b[0]), "r"(b[1]));
}

#define ASTRIDE 72

// EPI: 0 = raw float -> g_C1 (ld 256); 1 = *1/dv -> bf16 g_Acat (ld 1024);
//      2 = raw float -> g_h (ld 512)
template<int KT, int LDA, int LDB, int EPI>
__global__ void __launch_bounds__(256) k_gemm_t(const __nv_bfloat16* __restrict__ A,
                                                const __nv_bfloat16* __restrict__ B) {
    __shared__ __nv_bfloat16 As[128][ASTRIDE];
    __shared__ __nv_bfloat16 Bs[64][ASTRIDE];
    int tid = threadIdx.x;
    int lane = tid & 31;
    int warp = tid >> 5;
    int warp_m = warp & 3;
    int warp_n = warp >> 2;
    int rowBase = blockIdx.y * 128;
    int colBase = blockIdx.x * 64;
    int srow = tid >> 3;
    int scol = tid & 7;

    float acc[2][4][4];
    #pragma unroll
    for (int i = 0; i < 2; ++i)
        #pragma unroll
        for (int j = 0; j < 4; ++j)
            #pragma unroll
            for (int q = 0; q < 4; ++q) acc[i][j][q] = 0.f;

    const uint4* gA = reinterpret_cast<const uint4*>(A);
    const uint4* gB = reinterpret_cast<const uint4*>(B);
    const int lda4 = LDA / 8;    // uint4 per row
    const int ldb4 = LDB / 8;

    uint4 pa[4], pb[2];
    // prologue: load kc = 0
    {
        int kq = scol;
        #pragma unroll
        for (int p = 0; p < 4; ++p)
            pa[p] = gA[(size_t)(rowBase + p * 32 + srow) * lda4 + kq];
        #pragma unroll
        for (int p = 0; p < 2; ++p)
            pb[p] = gB[(size_t)(colBase + p * 32 + srow) * ldb4 + kq];
    }

    for (int kc = 0; kc < KT; ++kc) {
        __syncthreads();
        #pragma unroll
        for (int p = 0; p < 4; ++p)
            *reinterpret_cast<uint4*>(&As[p * 32 + srow][scol * 8]) = pa[p];
        #pragma unroll
        for (int p = 0; p < 2; ++p)
            *reinterpret_cast<uint4*>(&Bs[p * 32 + srow][scol * 8]) = pb[p];
        __syncthreads();
        if (kc + 1 < KT) {                    // prefetch next tile into regs
            int kq = (kc + 1) * 8 + scol;
            #pragma unroll
            for (int p = 0; p < 4; ++p)
                pa[p] = gA[(size_t)(rowBase + p * 32 + srow) * lda4 + kq];
            #pragma unroll
            for (int p = 0; p < 2; ++p)
                pb[p] = gB[(size_t)(colBase + p * 32 + srow) * ldb4 + kq];
        }
        #pragma unroll
        for (int k0 = 0; k0 < 64; k0 += 16) {
            uint32_t af[2][4], bf[4][2];
            int c = k0 + (lane & 3) * 2;
            #pragma unroll
            for (int tm = 0; tm < 2; ++tm) {
                int r = warp_m * 32 + tm * 16 + (lane >> 2);
                af[tm][0] = *reinterpret_cast<const uint32_t*>(&As[r][c]);
                af[tm][1] = *reinterpret_cast<const uint32_t*>(&As[r + 8][c]);
                af[tm][2] = *reinterpret_cast<const uint32_t*>(&As[r][c + 8]);
                af[tm][3] = *reinterpret_cast<const uint32_t*>(&As[r + 8][c + 8]);
            }
            #pragma unroll
            for (int tn = 0; tn < 4; ++tn) {
                int nr = warp_n * 32 + tn * 8 + (lane >> 2);
                bf[tn][0] = *reinterpret_cast<const uint32_t*>(&Bs[nr][c]);
                bf[tn][1] = *reinterpret_cast<const uint32_t*>(&Bs[nr][c + 8]);
            }
            #pragma unroll
            for (int tm = 0; tm < 2; ++tm)
                #pragma unroll
                for (int tn = 0; tn < 4; ++tn)
                    mma16816(acc[tm][tn], af[tm], bf[tn]);
        }
    }

    #pragma unroll
    for (int tm = 0; tm < 2; ++tm) {
        int r0 = rowBase + warp_m * 32 + tm * 16 + (lane >> 2);
        #pragma unroll
        for (int tn = 0; tn < 4; ++tn) {
            int c = colBase + warp_n * 32 + tn * 8 + (lane & 3) * 2;
            if (EPI == 0) {
                *reinterpret_cast<float2*>(&g_C1[(size_t)r0 * 256 + c]) =
                    make_float2(acc[tm][tn][0], acc[tm][tn][1]);
                *reinterpret_cast<float2*>(&g_C1[(size_t)(r0 + 8) * 256 + c]) =
                    make_float2(acc[tm][tn][2], acc[tm][tn][3]);
            } else if (EPI == 1) {
                if (r0 < N_NODES) {
                    float inv = 1.f / fmaxf(g_dv[r0], 1.f);
                    *reinterpret_cast<__nv_bfloat162*>(&g_Acat[(size_t)r0 * 1024 + c]) =
                        __floats2bfloat162_rn(acc[tm][tn][0] * inv, acc[tm][tn][1] * inv);
                }
                if (r0 + 8 < N_NODES) {
                    float inv = 1.f / fmaxf(g_dv[r0 + 8], 1.f);
                    *reinterpret_cast<__nv_bfloat162*>(&g_Acat[(size_t)(r0 + 8) * 1024 + c]) =
                        __floats2bfloat162_rn(acc[tm][tn][2] * inv, acc[tm][tn][3] * inv);
                }
            } else {
                if (r0 < N_NODES)
                    *reinterpret_cast<float2*>(&g_h[(size_t)r0 * D_OUT + c]) =
                        make_float2(acc[tm][tn][0], acc[tm][tn][1]);
                if (r0 + 8 < N_NODES)
                    *reinterpret_cast<float2*>(&g_h[(size_t)(r0 + 8) * D_OUT + c]) =
                        make_float2(acc[tm][tn][2], acc[tm][tn][3]);
            }
        }
    }
}

// ---------------- 4: C1 -> A1T (transpose + 1/d_e scale + bf16) -------------
__global__ void __launch_bounds__(256) k_tr1() {
    __shared__ __nv_bfloat16 sb[64][65];
    int m0 = blockIdx.x * 64;          // 80 tiles
    int d0 = blockIdx.y * 64;          // 4 tiles
    int t = threadIdx.x;
    #pragma unroll
    for (int p = 0; p < 4; ++p) {
        int m_l = p * 16 + (t >> 4);
        int d_l = (t & 15) * 4;
        int m = m0 + m_l;
        float inv = 1.f / fmaxf(g_de[m], 1.f);
        float4 v = *reinterpret_cast<const float4*>(g_C1 + (size_t)m * 256 + d0 + d_l);
        sb[m_l][d_l + 0] = __float2bfloat16_rn(v.x * inv);
        sb[m_l][d_l + 1] = __float2bfloat16_rn(v.y * inv);
        sb[m_l][d_l + 2] = __float2bfloat16_rn(v.z * inv);
        sb[m_l][d_l + 3] = __float2bfloat16_rn(v.w * inv);
    }
    __syncthreads();
    #pragma unroll
    for (int q = 0; q < 4; ++q) {
        int d_l = q * 16 + (t >> 4);
        int m_l = (t & 15) * 4;
        __nv_bfloat16 o[4];
        #pragma unroll
        for (int j = 0; j < 4; ++j) o[j] = sb[m_l + j][d_l];
        *reinterpret_cast<uint2*>(g_A1T + (size_t)(d0 + d_l) * HM_PAD + m0 + m_l) =
            *reinterpret_cast<uint2*>(o);
    }
}

// ---------------- 5: A_cat x_hi / x_lo parts (cols 256..1023) ---------------
__global__ void __launch_bounds__(384) k_prep_A(const float2* __restrict__ x2) {
    int row = blockIdx.x;
    int p = threadIdx.x + 128;           // bf162-pair index 128..511
    __nv_bfloat162* dst = reinterpret_cast<__nv_bfloat162*>(g_Acat) + (size_t)row * 512 + p;
    if (p < 384) {
        int q = (p < 256) ? (p - 128) : (p - 256);
        float2 f = x2[row * 128 + q];
        *dst = __floats2bfloat162_rn(f.x, f.y);      // x_hi
    } else {
        int q = p - 384;
        float2 f = x2[row * 128 + q];
        __nv_bfloat16 hx = __float2bfloat16_rn(f.x);
        __nv_bfloat16 hy = __float2bfloat16_rn(f.y);
        __nv_bfloat16 lx = __float2bfloat16_rn(f.x - __bfloat162float(hx));
        __nv_bfloat16 ly = __float2bfloat16_rn(f.y - __bfloat162float(hy));
        *dst = __halves2bfloat162(lx, ly);           // x_lo
    }
}

// ---------------- 6: LayerNorm + degree re-zero for next replay -------------
__global__ void __launch_bounds__(256) k_ln(const float* __restrict__ gamma,
                                            const float* __restrict__ beta,
                                            float* __restrict__ out) {
    int row = blockIdx.x;
    int t = threadIdx.x;
    int gid = row * 256 + t;
    if (gid < HM_PAD) g_de[gid] = 0.f;
    if (gid < N_NODES) g_dv[gid] = 0.f;

    const float* h = g_h + (size_t)row * D_OUT;
    float v0 = h[t], v1 = h[t + 256];
    float s = v0 + v1;
    float sq = v0 * v0 + v1 * v1;
    #pragma unroll
    for (int o = 16; o > 0; o >>= 1) {
        s  += __shfl_xor_sync(0xffffffffu, s,  o);
        sq += __shfl_xor_sync(0xffffffffu, sq, o);
    }
    __shared__ float ssum[8], ssq[8];
    __shared__ float s_mu, s_inv;
    int w = t >> 5, l = t & 31;
    if (l == 0) { ssum[w] = s; ssq[w] = sq; }
    __syncthreads();
    if (t == 0) {
        float ts = 0.f, tq = 0.f;
        #pragma unroll
        for (int i = 0; i < 8; ++i) { ts += ssum[i]; tq += ssq[i]; }
        float mu = ts * (1.f / (float)D_OUT);
        float var = tq * (1.f / (float)D_OUT) - mu * mu;
        s_mu = mu;
        s_inv = rsqrtf(var + 1e-5f);
    }
    __syncthreads();
    float mu = s_mu, inv = s_inv;
    out[(size_t)row * D_OUT + t]       = (v0 - mu) * inv * gamma[t]       + beta[t];
    out[(size_t)row * D_OUT + t + 256] = (v1 - mu) * inv * gamma[t + 256] + beta[t + 256];
}

// ---------------- launch -----------------------------------------------------
extern "C" void kernel_launch(void* const* d_in, const int* in_sizes, int n_in,
                              void* d_out, int out_size) {
    const float* x     = (const float*)d_in[0];
    const float* H     = (const float*)d_in[1];
    const float* Wn    = (const float*)d_in[2];
    const float* Wr    = (const float*)d_in[3];
    const float* gamma = (const float*)d_in[4];
    const float* beta  = (const float*)d_in[5];
    float* out = (float*)d_out;

    k_xt<<<dim3(313, 4), 256>>>(x);                       // 1
    k_prep<<<dim3(79, 313), 256>>>(H);                    // 2
    k_prep_W<<<(512 * 1024 + 255) / 256, 256>>>(Wn, Wr);  // 3

    // 4: edge sums = HbfT @ xbfT^T   [5120 x 256], K = 20032
    {
        const __nv_bfloat16* A; const __nv_bfloat16* B;
        cudaGetSymbolAddress((void**)&A, g_HbfT);
        cudaGetSymbolAddress((void**)&B, g_xbfT);
        k_gemm_t<HN_PAD / 64, HN_PAD, HN_PAD, 0><<<dim3(4, HM_PAD / 128), 256>>>(A, B);
    }
    k_tr1<<<dim3(80, 4), 256>>>();                        // 5

    // 6: node sums = Hbf @ A1T^T    [20096 x 256], K = 5120 -> g_Acat cols 0..255
    {
        const __nv_bfloat16* A; const __nv_bfloat16* B;
        cudaGetSymbolAddress((void**)&A, g_Hbf);
        cudaGetSymbolAddress((void**)&B, g_A1T);
        k_gemm_t<HM_PAD / 64, HM_PAD, HM_PAD, 1><<<dim3(4, N_PAD / 128), 256>>>(A, B);
    }
    k_prep_A<<<N_NODES, 384>>>((const float2*)x);         // 7

    // 8: h = A_cat @ W_t^T  [20096 x 512], K = 1024
    {
        const __nv_bfloat16* A; const __nv_bfloat16* B;
        cudaGetSymbolAddress((void**)&A, g_Acat);
        cudaGetSymbolAddress((void**)&B, g_Wt);
        k_gemm_t<16, 1024, 1024, 2><<<dim3(8, N_PAD / 128), 256>>>(A, B);
    }
    k_ln<<<N_NODES, 256>>>(gamma, beta, out);             // 9
}